// round 15
// baseline (speedup 1.0000x reference)
#include <cuda_runtime.h>
#include <cuda_fp16.h>
#include <math.h>
#include <stdint.h>

constexpr int NV = 50000, NC = 210000, NE = 630000, NG = 32, ROUNDS = 16;

// ----------------- device scratch -----------------
__device__ float  g_vars   [NV*64];
__device__ float  g_clauses[NC*64];
__device__ __half g_lits   [2*NV*64];
__device__ __half g_sig    [NV*64];
__device__ __half g_cl     [NC*64];
__device__ __half g_cd     [NC*128];
__device__ __half g_vraw   [NV*64];
__device__ int    g_deg    [2*NV];
__device__ int    g_off    [2*NV+1];
__device__ int    g_cur    [2*NV];
__device__ int    g_pcl    [NE];
__device__ float  g_dw     [2*NV];
__device__ float  g_vdw    [NV];
__device__ int    g_gcnt   [2*NG];
__device__ float  g_statC  [2*NG*64];   // zero-init; k_fin2 self-clears
__device__ float  g_statV  [2*NG*64];
__device__ float  g_meanC  [NG*64];
__device__ float  g_rsigC  [NG*64];
__device__ float  g_meanV  [NG*64];
__device__ float  g_rsigV  [NG*64];
// fp16 weights, TRANSPOSED [n][k] padded
__device__ __half g_qW0h[64*72];
__device__ __half g_qW1h[64*64];
__device__ __half g_cW0h[128*128];
__device__ __half g_cW1h[128*128];
__device__ __half g_uW0h[128*256];
__device__ __half g_uW1h[128*128];
__device__ __half g_uW2h[64*128];
__device__ __half g_oW0h[64*64];

__device__ __forceinline__ float lrelu(float x){ return x > 0.f ? x : 0.2f*x; }
__device__ __forceinline__ float sp(float x){ return fmaxf(x,0.f) + log1pf(expf(-fabsf(x))); }

__device__ __forceinline__ void mma16(float* c, const uint32_t* a, const uint32_t* b){
  asm("mma.sync.aligned.m16n8k16.row.col.f32.f16.f16.f32 "
      "{%0,%1,%2,%3},{%4,%5,%6,%7},{%8,%9},{%0,%1,%2,%3};"
      : "+f"(c[0]),"+f"(c[1]),"+f"(c[2]),"+f"(c[3])
      : "r"(a[0]),"r"(a[1]),"r"(a[2]),"r"(a[3]),"r"(b[0]),"r"(b[1]));
}
__device__ __forceinline__ void ldmA4(uint32_t* a, uint32_t addr){
  asm volatile("ldmatrix.sync.aligned.m8n8.x4.shared.b16 {%0,%1,%2,%3}, [%4];"
    : "=r"(a[0]),"=r"(a[1]),"=r"(a[2]),"=r"(a[3]) : "r"(addr));
}
__device__ __forceinline__ void ldmB2(uint32_t* b, uint32_t addr){
  asm volatile("ldmatrix.sync.aligned.m8n8.x2.shared.b16 {%0,%1}, [%2];"
    : "=r"(b[0]),"=r"(b[1]) : "r"(addr));
}
__device__ __forceinline__ void load8f(const float* A, size_t off, __half2* h){
  float4 v0 = *(const float4*)(A+off), v1 = *(const float4*)(A+off+4);
  h[0]=__floats2half2_rn(v0.x, v0.y); h[1]=__floats2half2_rn(v0.z, v0.w);
  h[2]=__floats2half2_rn(v1.x, v1.y); h[3]=__floats2half2_rn(v1.z, v1.w);
}

// fused pair-norm apply for 8 state cols: new = (prev-mean)*rsig*0.25 + 0.1*state
__device__ __forceinline__ void apply8(float* state, const __half* prev,
    int pstride, int poff, const float* mean, const float* rsig,
    int gg, int row, int col0, int first, __half2* h){
  float nv[8];
  if(first){
    #pragma unroll
    for(int e=0;e<8;e++) nv[e]=1.f;
  } else {
    uint4 pu = *(const uint4*)&prev[(size_t)row*pstride + poff + col0];
    __half2* ph = (__half2*)&pu;
    const float* mb = &mean[gg*64 + col0];
    const float* rb = &rsig[gg*64 + col0];
    const float* sb = &state[(size_t)row*64 + col0];
    float4 m0=*(const float4*)mb, m1=*(const float4*)(mb+4);
    float4 r0=*(const float4*)rb, r1=*(const float4*)(rb+4);
    float4 s0=*(const float4*)sb, s1=*(const float4*)(sb+4);
    float2 p0=__half22float2(ph[0]), p1=__half22float2(ph[1]);
    float2 p2=__half22float2(ph[2]), p3=__half22float2(ph[3]);
    nv[0]=(p0.x-m0.x)*r0.x*0.25f + 0.1f*s0.x;
    nv[1]=(p0.y-m0.y)*r0.y*0.25f + 0.1f*s0.y;
    nv[2]=(p1.x-m0.z)*r0.z*0.25f + 0.1f*s0.z;
    nv[3]=(p1.y-m0.w)*r0.w*0.25f + 0.1f*s0.w;
    nv[4]=(p2.x-m1.x)*r1.x*0.25f + 0.1f*s1.x;
    nv[5]=(p2.y-m1.y)*r1.y*0.25f + 0.1f*s1.y;
    nv[6]=(p3.x-m1.z)*r1.z*0.25f + 0.1f*s1.z;
    nv[7]=(p3.y-m1.w)*r1.w*0.25f + 0.1f*s1.w;
  }
  float* sw = &state[(size_t)row*64 + col0];
  *(float4*)sw     = make_float4(nv[0],nv[1],nv[2],nv[3]);
  *(float4*)(sw+4) = make_float4(nv[4],nv[5],nv[6],nv[7]);
  h[0]=__floats2half2_rn(nv[0],nv[1]); h[1]=__floats2half2_rn(nv[2],nv[3]);
  h[2]=__floats2half2_rn(nv[4],nv[5]); h[3]=__floats2half2_rn(nv[6],nv[7]);
}

// ----------------- setup -----------------
__global__ void k_count(const int* __restrict__ lit, const int* __restrict__ vg,
                        const int* __restrict__ cg){
  int i = blockIdx.x*blockDim.x + threadIdx.x, s = gridDim.x*blockDim.x;
  for(int j=i;j<NE;j+=s) atomicAdd(&g_deg[lit[j]],1);
  for(int j=i;j<NV;j+=s) atomicAdd(&g_gcnt[NG+vg[j]],1);
  for(int j=i;j<NC;j+=s) atomicAdd(&g_gcnt[cg[j]],1);
}
__global__ void k_scan(){
  __shared__ int sh[1024];
  __shared__ int carry;
  int tid = threadIdx.x;
  if(tid==0) carry=0;
  __syncthreads();
  for(int base=0; base<2*NV; base+=1024){
    int i = base + tid;
    int v = (i < 2*NV) ? g_deg[i] : 0;
    sh[tid] = v; __syncthreads();
    for(int d=1; d<1024; d<<=1){
      int t = (tid>=d) ? sh[tid-d] : 0;
      __syncthreads();
      sh[tid] += t;
      __syncthreads();
    }
    int excl = sh[tid] - v;
    int total = sh[1023];
    int c = carry;
    if(i < 2*NV){ g_off[i] = c + excl; g_cur[i] = c + excl; }
    __syncthreads();
    if(tid==0) carry = c + total;
    __syncthreads();
  }
  if(tid==0) g_off[2*NV] = carry;
  __syncthreads();
  for(int i=tid;i<2*NV;i+=1024) g_dw[i] = rsqrtf(fmaxf((float)g_deg[i],1.f));
  for(int i=tid;i<NV;i+=1024)  g_vdw[i] = 4.f*rsqrtf(fmaxf((float)(g_deg[i]+g_deg[NV+i]),1.f));
  __syncthreads();
  for(int i=tid;i<2*NV;i+=1024) g_deg[i] = 0;   // clean for next graph replay
}
__device__ void wtconv(const float* W, __half* WT, int K, int N, int Kp, int i, int s){
  for(int j=i;j<N*Kp;j+=s){
    int n = j/Kp, k = j%Kp;
    WT[j] = __float2half_rn((k < K) ? W[(size_t)k*N + n] : 0.f);
  }
}
__global__ void k_fillw(const int* __restrict__ lit,
                        const float* q0,const float* q1,const float* c0,const float* c1,
                        const float* u0,const float* u1,const float* u2,const float* o0){
  int i = blockIdx.x*blockDim.x + threadIdx.x, s = gridDim.x*blockDim.x;
  for(int e=i;e<NE;e+=s){
    int l = lit[e];
    int p = atomicAdd(&g_cur[l],1);
    g_pcl[p] = e/3;
  }
  wtconv(q0, g_qW0h,  68,  64,  72, i, s);
  wtconv(q1, g_qW1h,  64,  64,  64, i, s);
  wtconv(c0, g_cW0h, 128, 128, 128, i, s);
  wtconv(c1, g_cW1h, 128, 128, 128, i, s);
  wtconv(u0, g_uW0h, 256, 128, 256, i, s);
  wtconv(u1, g_uW1h, 128, 128, 128, i, s);
  wtconv(u2, g_uW2h, 128,  64, 128, i, s);
  wtconv(o0, g_oW0h,  64,  64,  64, i, s);
}

// ----------------- fused multi-layer MLP -----------------
constexpr int FM_PH  = 72;
constexpr int FM_PHH = 136;
constexpr int FM_SMEM = (128*FM_PH + 128*FM_PH + 128*FM_PHH) * 2;

template<int NIN, int NWo>
__device__ __forceinline__ void gemm_smem(
    float (&acc)[2][NWo][4], const __half* __restrict__ WT, int Nout,
    __half* sW, uint32_t sWb, uint32_t sHb,
    int tid, int lane, int r0, int cb){
  constexpr int KC = 64;
  int lr = lane & 7, bsel = ((lane>>3)&1)*8, asel = ((lane>>4)&1)*8;
  for(int ch=0; ch<NIN/KC; ch++){
    __syncthreads();
    for(int i=tid; i<Nout*(KC/8); i+=256){
      int n = i/(KC/8), kg = i%(KC/8);
      *(uint4*)&sW[n*FM_PH + kg*8] = *(const uint4*)&WT[(size_t)n*NIN + ch*KC + kg*8];
    }
    __syncthreads();
    #pragma unroll
    for(int s=0;s<KC/16;s++){
      int wks = s*16, ks = ch*KC + s*16;
      uint32_t bfr[NWo][2];
      #pragma unroll
      for(int j=0;j<NWo;j++){
        int nrow = cb + j*8 + lr;
        ldmB2(bfr[j], sWb + (uint32_t)(nrow*FM_PH + wks + bsel)*2);
      }
      uint32_t afr[2][4];
      #pragma unroll
      for(int mf=0;mf<2;mf++){
        int row = r0 + mf*16 + lr + ((lane>>3)&1)*8;
        ldmA4(afr[mf], sHb + (uint32_t)(row*FM_PHH + ks + asel)*2);
      }
      #pragma unroll
      for(int mf=0;mf<2;mf++)
        #pragma unroll
        for(int j=0;j<NWo;j++) mma16(acc[mf][j], afr[mf], bfr[j]);
    }
  }
}
template<int NWo>
__device__ __forceinline__ void storeH(float (&acc)[2][NWo][4], __half* sH,
                                       int r0,int cb,int g,int tg){
  #pragma unroll
  for(int mf=0;mf<2;mf++){
    int rr = r0 + mf*16 + g;
    #pragma unroll
    for(int j=0;j<NWo;j++){
      int col = cb + j*8 + 2*tg;
      *(__half2*)&sH[rr*FM_PHH + col]     = __floats2half2_rn(lrelu(acc[mf][j][0]), lrelu(acc[mf][j][1]));
      *(__half2*)&sH[(rr+8)*FM_PHH + col] = __floats2half2_rn(lrelu(acc[mf][j][2]), lrelu(acc[mf][j][3]));
    }
  }
}
template<int NWo>
__device__ __forceinline__ void initB(float (&acc)[2][NWo][4], const float* b, int cb, int tg){
  #pragma unroll
  for(int j=0;j<NWo;j++){
    int col = cb + j*8 + 2*tg;
    float b0v = b[col], b1v = b[col+1];
    #pragma unroll
    for(int mf=0;mf<2;mf++){
      acc[mf][j][0]=b0v; acc[mf][j][1]=b1v; acc[mf][j][2]=b0v; acc[mf][j][3]=b1v;
    }
  }
}

// MODE 0 = query MLP (vars apply + noise concat), 1 = clause MLP (clauses apply +
// fused cl gather/exp), 2 = update MLP (fused uin gather: grad/vars/loss)
// ACT: 0 = store half, 2 = lits epilogue. STATS: accumulate final-64-col stats.
template<int MODE, int K0,int K1,int N1,int N2,int N3,int ACT,int STATS>
__global__ void __launch_bounds__(256) k_fmlp(
    float* __restrict__ state, const float* __restrict__ A1f,
    const int* __restrict__ lit,
    const __half* __restrict__ prev, int pstride, int poff,
    const float* __restrict__ pmean, const float* __restrict__ prsig,
    const int* __restrict__ gid, int first,
    const __half* __restrict__ WT0, const float* __restrict__ b0,
    const __half* __restrict__ WT1, const float* __restrict__ b1,
    const __half* __restrict__ WT2, const float* __restrict__ b2,
    void* Cv, int M, float* __restrict__ statbuf){
  constexpr int K  = K0 + K1;
  constexpr int Kp = (K + 7) & ~7;
  constexpr int KC = 64;
  constexpr int CW = 2, RW = 4;
  constexpr int NW1 = N1/8/CW;
  constexpr int NF  = (N3>0) ? N3 : N2;
  constexpr int NWF = NF/8/CW;
  extern __shared__ __align__(16) __half smem[];
  __half* sA = smem;
  __half* sW = sA + 128*FM_PH;
  __half* sH = sW + 128*FM_PH;
  int tid = threadIdx.x;
  int w = tid >> 5, lane = tid & 31;
  int g = lane >> 2, tg = lane & 3;
  int wr = w % RW, wc = w / RW;
  int base = blockIdx.x * 128;
  int r0 = wr * 32;
  uint32_t sAb = (uint32_t)__cvta_generic_to_shared(sA);
  uint32_t sWb = (uint32_t)__cvta_generic_to_shared(sW);
  uint32_t sHb = (uint32_t)__cvta_generic_to_shared(sH);
  int lr = lane & 7, bsel = ((lane>>3)&1)*8, asel = ((lane>>4)&1)*8;

  // ---- Layer 1 ----
  int cb1 = wc * NW1 * 8;
  float acc1[2][NW1][4];
  initB(acc1, b0, cb1, tg);
  constexpr int NCH1 = (K + KC - 1)/KC;
  for(int ch=0; ch<NCH1; ch++){
    int k0c = ch*KC;
    __syncthreads();
    for(int i=tid; i<N1*(KC/8); i+=256){
      int n = i/(KC/8), kg = i%(KC/8);
      int col0 = k0c + kg*8;
      uint4 u = make_uint4(0u,0u,0u,0u);
      if(col0 + 8 <= Kp) u = *(const uint4*)&WT0[(size_t)n*Kp + col0];
      *(uint4*)&sW[n*FM_PH + kg*8] = u;
    }
    for(int i=tid; i<128*(KC/8); i+=256){
      int r = i/(KC/8), kg = i%(KC/8);
      int row = base + r;
      int f0 = kg*8;
      __half2 h[4];
      h[0]=h[1]=h[2]=h[3]=__float2half2_rn(0.f);
      if(row < M){
        if constexpr (MODE==0){
          if(ch==0) apply8(state, prev, pstride, poff, pmean, prsig, gid[row], row, f0, first, h);
          else if(kg==0){
            float4 nv = *(const float4*)&A1f[(size_t)row*4];
            h[0]=__floats2half2_rn(nv.x,nv.y); h[1]=__floats2half2_rn(nv.z,nv.w);
          }
        } else if constexpr (MODE==1){
          if(ch==0) apply8(state, prev, pstride, poff, pmean, prsig, gid[row], row, f0, first, h);
          else {
            int e = 3*row;
            int l0=lit[e], l1=lit[e+1], l2=lit[e+2];
            uint4 ua=*(const uint4*)&g_lits[(size_t)l0*64+f0];
            uint4 ub=*(const uint4*)&g_lits[(size_t)l1*64+f0];
            uint4 uc=*(const uint4*)&g_lits[(size_t)l2*64+f0];
            __half2* pa=(__half2*)&ua; __half2* pb=(__half2*)&ub; __half2* pc=(__half2*)&uc;
            __half2 clh[4];
            #pragma unroll
            for(int p=0;p<4;p++){
              float2 fa=__half22float2(pa[p]), fb=__half22float2(pb[p]), fcv=__half22float2(pc[p]);
              float c0v = expf(-(fa.x+fb.x+fcv.x));
              float c1v = expf(-(fa.y+fb.y+fcv.y));
              clh[p] = __floats2half2_rn(c0v, c1v);
              h[p]   = __floats2half2_rn(4.f*c0v, 4.f*c1v);
            }
            *(uint4*)&g_cl[(size_t)row*64+f0] = *(uint4*)clh;
          }
        } else { // MODE==2: fused uin gather
          if(ch==1){
            load8f(state, (size_t)row*64 + f0, h);
          } else if(ch==0){
            float sacc[8]={0,0,0,0,0,0,0,0}, nacc[8]={0,0,0,0,0,0,0,0};
            int p0=g_off[row], p1=g_off[row+1];
            for(int e=p0;e<p1;e++){
              int c=g_pcl[e];
              uint4 u=*(const uint4*)&g_cl[(size_t)c*64+f0];
              __half2* ph=(__half2*)&u;
              #pragma unroll
              for(int p=0;p<4;p++){ float2 f2=__half22float2(ph[p]); sacc[2*p]+=f2.x; sacc[2*p+1]+=f2.y; }
            }
            int n0=g_off[NV+row], n1=g_off[NV+row+1];
            for(int e=n0;e<n1;e++){
              int c=g_pcl[e];
              uint4 u=*(const uint4*)&g_cl[(size_t)c*64+f0];
              __half2* ph=(__half2*)&u;
              #pragma unroll
              for(int p=0;p<4;p++){ float2 f2=__half22float2(ph[p]); nacc[2*p]+=f2.x; nacc[2*p+1]+=f2.y; }
            }
            uint4 us=*(const uint4*)&g_sig[(size_t)row*64+f0];
            __half2* ps=(__half2*)&us;
            float vdw=g_vdw[row];
            #pragma unroll
            for(int p=0;p<4;p++){
              float2 sg=__half22float2(ps[p]);
              float g0=(-sg.x*sacc[2*p]   + (1.f-sg.x)*nacc[2*p]  )*vdw;
              float g1=(-sg.y*sacc[2*p+1] + (1.f-sg.y)*nacc[2*p+1])*vdw;
              h[p]=__floats2half2_rn(g0,g1);
            }
          } else { // ch==2 (pos loss) / ch==3 (neg loss)
            float acc8[8]={0,0,0,0,0,0,0,0};
            int off0 = (ch==2)? row : NV+row;
            int e0=g_off[off0], e1=g_off[off0+1];
            for(int e=e0;e<e1;e++){
              int c=g_pcl[e];
              uint4 u=*(const uint4*)&g_cd[(size_t)c*128+f0];
              __half2* ph=(__half2*)&u;
              #pragma unroll
              for(int p=0;p<4;p++){ float2 f2=__half22float2(ph[p]); acc8[2*p]+=f2.x; acc8[2*p+1]+=f2.y; }
            }
            float dwv = g_dw[off0];
            #pragma unroll
            for(int p=0;p<4;p++) h[p]=__floats2half2_rn(acc8[2*p]*dwv, acc8[2*p+1]*dwv);
          }
        }
      }
      *(uint4*)&sA[r*FM_PH + kg*8] = *(uint4*)h;
    }
    __syncthreads();
    #pragma unroll
    for(int s=0;s<KC/16;s++){
      int ks = s*16;
      uint32_t bfr[NW1][2];
      #pragma unroll
      for(int j=0;j<NW1;j++){
        int nrow = cb1 + j*8 + lr;
        ldmB2(bfr[j], sWb + (uint32_t)(nrow*FM_PH + ks + bsel)*2);
      }
      uint32_t afr[2][4];
      #pragma unroll
      for(int mf=0;mf<2;mf++){
        int row = r0 + mf*16 + lr + ((lane>>3)&1)*8;
        ldmA4(afr[mf], sAb + (uint32_t)(row*FM_PH + ks + asel)*2);
      }
      #pragma unroll
      for(int mf=0;mf<2;mf++)
        #pragma unroll
        for(int j=0;j<NW1;j++) mma16(acc1[mf][j], afr[mf], bfr[j]);
    }
  }
  storeH(acc1, sH, r0, cb1, g, tg);

  // ---- Layer 2 (+3) ----
  float facc[2][NWF][4];
  int cbF = wc * NWF * 8;
  if constexpr (N3 == 0){
    initB(facc, b1, cbF, tg);
    gemm_smem<N1,NWF>(facc, WT1, N2, sW, sWb, sHb, tid, lane, r0, cbF);
  } else {
    constexpr int NW2 = N2/8/CW;
    int cb2 = wc * NW2 * 8;
    float acc2[2][NW2][4];
    initB(acc2, b1, cb2, tg);
    gemm_smem<N1,NW2>(acc2, WT1, N2, sW, sWb, sHb, tid, lane, r0, cb2);
    __syncthreads();
    storeH(acc2, sH, r0, cb2, g, tg);
    initB(facc, b2, cbF, tg);
    gemm_smem<N2,NWF>(facc, WT2, N3, sW, sWb, sHb, tid, lane, r0, cbF);
  }

  // ---- epilogue ----
  if constexpr (ACT == 0){
    __half* C = (__half*)Cv;
    #pragma unroll
    for(int mf=0;mf<2;mf++){
      int row0 = base + r0 + mf*16 + g;
      int row1 = row0 + 8;
      #pragma unroll
      for(int j=0;j<NWF;j++){
        int col = cbF + j*8 + 2*tg;
        if(row0 < M) *(__half2*)&C[(size_t)row0*NF + col] = __floats2half2_rn(facc[mf][j][0], facc[mf][j][1]);
        if(row1 < M) *(__half2*)&C[(size_t)row1*NF + col] = __floats2half2_rn(facc[mf][j][2], facc[mf][j][3]);
      }
    }
  } else { // ACT==2: lits epilogue
    #pragma unroll
    for(int mf=0;mf<2;mf++){
      #pragma unroll
      for(int j=0;j<NWF;j++){
        int col = cbF + j*8 + 2*tg;
        #pragma unroll
        for(int h=0;h<2;h++){
          int row = base + r0 + mf*16 + g + 8*h;
          if(row < M){
            float qa = facc[mf][j][2*h], qb = facc[mf][j][2*h+1];
            *(__half2*)&g_lits[(size_t)row*64 + col]      = __floats2half2_rn(sp(qa), sp(qb));
            *(__half2*)&g_lits[(size_t)(NV+row)*64 + col] = __floats2half2_rn(sp(-qa), sp(-qb));
            *(__half2*)&g_sig [(size_t)row*64 + col]      =
                __floats2half2_rn(1.f/(1.f+expf(-qa)), 1.f/(1.f+expf(-qb)));
          }
        }
      }
    }
  }

  // ---- fused group stats on final output cols [NF-64, NF) ----
  if constexpr (STATS){
    int glast = min(base+127, M-1);
    int g0 = gid[base];
    bool fast = (g0 == gid[glast]);
    #pragma unroll
    for(int j=0;j<NWF;j++){
      int col = cbF + j*8 + 2*tg;
      if(col >= NF-64){
        int sc = col - (NF-64);
        float s0=0.f,q0=0.f,s1=0.f,q1=0.f;
        #pragma unroll
        for(int mf=0;mf<2;mf++){
          #pragma unroll
          for(int h=0;h<2;h++){
            int row = base + r0 + mf*16 + g + 8*h;
            if(row < M){
              float v0=facc[mf][j][2*h], v1=facc[mf][j][2*h+1];
              if(fast){ s0+=v0; q0+=v0*v0; s1+=v1; q1+=v1*v1; }
              else {
                int gr = gid[row];
                atomicAdd(&statbuf[gr*64+sc], v0);
                atomicAdd(&statbuf[NG*64+gr*64+sc], v0*v0);
                atomicAdd(&statbuf[gr*64+sc+1], v1);
                atomicAdd(&statbuf[NG*64+gr*64+sc+1], v1*v1);
              }
            }
          }
        }
        if(fast){
          #pragma unroll
          for(int o=16;o>=4;o>>=1){
            s0+=__shfl_down_sync(0xffffffffu,s0,o);
            q0+=__shfl_down_sync(0xffffffffu,q0,o);
            s1+=__shfl_down_sync(0xffffffffu,s1,o);
            q1+=__shfl_down_sync(0xffffffffu,q1,o);
          }
          if(lane < 4){
            atomicAdd(&statbuf[g0*64+sc], s0);
            atomicAdd(&statbuf[NG*64+g0*64+sc], q0);
            atomicAdd(&statbuf[g0*64+sc+1], s1);
            atomicAdd(&statbuf[NG*64+g0*64+sc+1], q1);
          }
        }
      }
    }
  }
}

// ----------------- head (fused final clause apply, read-only) ---------------
__global__ void __launch_bounds__(256) k_head(
    const int* __restrict__ cg, const __half* __restrict__ WT,
    const float* __restrict__ b, float* __restrict__ C, int M,
    const float* __restrict__ w2, const float* __restrict__ b2){
  constexpr int KC = 64, PH = 72, N = 64, NW = 8;
  __shared__ __align__(16) __half sA[128*PH];
  __shared__ __align__(16) __half sW[N*PH];
  int tid = threadIdx.x;
  int w = tid >> 5, lane = tid & 31;
  int g = lane >> 2, tg = lane & 3;
  int base = blockIdx.x * 128;
  int r0 = w * 16;
  float acc[NW][4];
  #pragma unroll
  for(int j=0;j<NW;j++){
    int col = j*8 + 2*tg;
    float b0v = b[col], b1v = b[col+1];
    acc[j][0]=b0v; acc[j][1]=b1v; acc[j][2]=b0v; acc[j][3]=b1v;
  }
  uint32_t sAb = (uint32_t)__cvta_generic_to_shared(sA);
  uint32_t sWb = (uint32_t)__cvta_generic_to_shared(sW);
  for(int i=tid; i<N*(KC/8); i+=256){
    int n = i/(KC/8), kg = i%(KC/8);
    *(uint4*)&sW[n*PH + kg*8] = *(const uint4*)&WT[(size_t)n*64 + kg*8];
  }
  for(int i=tid; i<128*(KC/8); i+=256){
    int r = i/(KC/8), kg = i%(KC/8);
    int row = base + r;
    int col0 = kg*8;
    __half2 h[4];
    h[0]=h[1]=h[2]=h[3]=__float2half2_rn(0.f);
    if(row < M){
      int gg = cg[row];
      uint4 pu = *(const uint4*)&g_cd[(size_t)row*128 + 64 + col0];
      __half2* ph = (__half2*)&pu;
      const float* mb = &g_meanC[gg*64 + col0];
      const float* rb = &g_rsigC[gg*64 + col0];
      const float* sb = &g_clauses[(size_t)row*64 + col0];
      float4 m0=*(const float4*)mb, m1=*(const float4*)(mb+4);
      float4 rr0=*(const float4*)rb, rr1=*(const float4*)(rb+4);
      float4 s0=*(const float4*)sb, s1=*(const float4*)(sb+4);
      float2 p0=__half22float2(ph[0]), p1=__half22float2(ph[1]);
      float2 p2=__half22float2(ph[2]), p3=__half22float2(ph[3]);
      float nv0=(p0.x-m0.x)*rr0.x*0.25f + 0.1f*s0.x;
      float nv1=(p0.y-m0.y)*rr0.y*0.25f + 0.1f*s0.y;
      float nv2=(p1.x-m0.z)*rr0.z*0.25f + 0.1f*s0.z;
      float nv3=(p1.y-m0.w)*rr0.w*0.25f + 0.1f*s0.w;
      float nv4=(p2.x-m1.x)*rr1.x*0.25f + 0.1f*s1.x;
      float nv5=(p2.y-m1.y)*rr1.y*0.25f + 0.1f*s1.y;
      float nv6=(p3.x-m1.z)*rr1.z*0.25f + 0.1f*s1.z;
      float nv7=(p3.y-m1.w)*rr1.w*0.25f + 0.1f*s1.w;
      h[0]=__floats2half2_rn(nv0,nv1); h[1]=__floats2half2_rn(nv2,nv3);
      h[2]=__floats2half2_rn(nv4,nv5); h[3]=__floats2half2_rn(nv6,nv7);
    }
    *(uint4*)&sA[r*PH + col0] = *(uint4*)h;
  }
  __syncthreads();
  int lr = lane & 7;
  #pragma unroll
  for(int s=0;s<KC/16;s++){
    int ks = s*16;
    uint32_t bfr[NW][2];
    #pragma unroll
    for(int j=0;j<NW;j++){
      int nrow = j*8 + lr;
      ldmB2(bfr[j], sWb + (uint32_t)(nrow*PH + ks + ((lane>>3)&1)*8)*2);
    }
    uint32_t afr[4];
    {
      int row = r0 + lr + ((lane>>3)&1)*8;
      ldmA4(afr, sAb + (uint32_t)(row*PH + ks + ((lane>>4)&1)*8)*2);
    }
    #pragma unroll
    for(int j=0;j<NW;j++) mma16(acc[j], afr, bfr[j]);
  }
  float p0 = 0.f, p1 = 0.f;
  #pragma unroll
  for(int j=0;j<NW;j++){
    int col = j*8 + 2*tg;
    float wa = w2[col], wb = w2[col+1];
    p0 += lrelu(acc[j][0])*wa + lrelu(acc[j][1])*wb;
    p1 += lrelu(acc[j][2])*wa + lrelu(acc[j][3])*wb;
  }
  #pragma unroll
  for(int o=2;o>0;o>>=1){
    p0 += __shfl_down_sync(0xffffffffu, p0, o, 4);
    p1 += __shfl_down_sync(0xffffffffu, p1, o, 4);
  }
  if(tg == 0){
    int row0 = base + r0 + g;
    int row1 = row0 + 8;
    float bb = b2[0];
    if(row0 < M){
      float lg = p0 + bb;
      C[row0] = 1.f/(1.f+expf(-lg)); C[NC + row0] = sp(lg);
    }
    if(row1 < M){
      float lg = p1 + bb;
      C[row1] = 1.f/(1.f+expf(-lg)); C[NC + row1] = sp(lg);
    }
  }
  if(blockIdx.x == 0 && tid < 2*NG) g_gcnt[tid] = 0;
}

// mean/rsig for BOTH C and V stats; self-clears stat buffers
__global__ void k_fin2(){
  int i = blockIdx.x*blockDim.x + threadIdx.x;
  if(i >= 2*NG*64) return;
  bool isV = (i >= NG*64);
  int ii = isV ? i - NG*64 : i;
  int gg = ii >> 6;
  float* stat = isV ? g_statV : g_statC;
  float cnt = (float)g_gcnt[(isV ? NG : 0) + gg];
  float inv = 1.f / fmaxf(cnt, 1.f);
  float m = stat[ii] * inv;
  float var = stat[NG*64 + ii] * inv - m*m;
  if(isV){ g_meanV[ii]=m; g_rsigV[ii]=rsqrtf(fmaxf(var,0.f)+1e-6f); }
  else   { g_meanC[ii]=m; g_rsigC[ii]=rsqrtf(fmaxf(var,0.f)+1e-6f); }
  stat[ii]=0.f; stat[NG*64+ii]=0.f;
}

// ----------------- host -----------------
static void* sym(const void* s){ void* p=nullptr; cudaGetSymbolAddress(&p, s); return p; }

extern "C" void kernel_launch(void* const* d_in, const int* in_sizes, int n_in,
                              void* d_out, int out_size){
  const int*   lit   = (const int*)d_in[0];
  const int*   vg    = (const int*)d_in[2];
  const int*   cg    = (const int*)d_in[3];
  const float* noise = (const float*)d_in[4];
  const float *qW0=(const float*)d_in[5],  *qb0=(const float*)d_in[6];
  const float *qW1=(const float*)d_in[7],  *qb1=(const float*)d_in[8];
  const float *cW0=(const float*)d_in[9],  *cb0=(const float*)d_in[10];
  const float *cW1=(const float*)d_in[11], *cb1=(const float*)d_in[12];
  const float *uW0=(const float*)d_in[13], *ub0=(const float*)d_in[14];
  const float *uW1=(const float*)d_in[15], *ub1=(const float*)d_in[16];
  const float *uW2=(const float*)d_in[17], *ub2=(const float*)d_in[18];
  const float *oW0=(const float*)d_in[19], *ob0=(const float*)d_in[20];
  const float *oW1=(const float*)d_in[21], *ob1=(const float*)d_in[22];
  float* out = (float*)d_out;

  float  *p_vars  = (float*)sym(g_vars),   *p_claus = (float*)sym(g_clauses);
  float  *p_statC = (float*)sym(g_statC),  *p_statV = (float*)sym(g_statV);
  float  *p_meanC = (float*)sym(g_meanC),  *p_rsigC = (float*)sym(g_rsigC);
  float  *p_meanV = (float*)sym(g_meanV),  *p_rsigV = (float*)sym(g_rsigV);
  __half *p_cd = (__half*)sym(g_cd);
  __half *p_vraw = (__half*)sym(g_vraw);
  __half *t_q0 = (__half*)sym(g_qW0h), *t_q1 = (__half*)sym(g_qW1h);
  __half *t_c0 = (__half*)sym(g_cW0h), *t_c1 = (__half*)sym(g_cW1h);
  __half *t_u0 = (__half*)sym(g_uW0h), *t_u1 = (__half*)sym(g_uW1h), *t_u2 = (__half*)sym(g_uW2h);
  __half *t_o0 = (__half*)sym(g_oW0h);
  const __half* hnull = nullptr;

  auto fq = k_fmlp<0, 64,4,  64, 64, 0, 2, 0>;
  auto fc = k_fmlp<1, 64,64,128,128, 0, 0, 1>;
  auto fu = k_fmlp<2,256, 0,128,128,64, 0, 1>;
  cudaFuncSetAttribute(fq, cudaFuncAttributeMaxDynamicSharedMemorySize, FM_SMEM);
  cudaFuncSetAttribute(fc, cudaFuncAttributeMaxDynamicSharedMemorySize, FM_SMEM);
  cudaFuncSetAttribute(fu, cudaFuncAttributeMaxDynamicSharedMemorySize, FM_SMEM);

  const int T = 256;
  auto B = [](long n){ return (int)((n + 255) / 256); };
  int mbV = (NV + 127) / 128, mbC = (NC + 127) / 128;

  k_count<<<1024, T>>>(lit, vg, cg);
  k_scan<<<1, 1024>>>();
  k_fillw<<<256, T>>>(lit, qW0, qW1, cW0, cW1, uW0, uW1, uW2, oW0);

  for(int t = 0; t < ROUNDS; t++){
    const float* nz = noise + (size_t)t * NV * 4;
    int first = (t == 0) ? 1 : 0;
    // query MLP: fused vars apply + noise concat + lits epilogue
    fq<<<mbV, T, FM_SMEM>>>(p_vars, nz, nullptr, p_vraw, 64, 0, p_meanV, p_rsigV, vg, first,
                            t_q0, qb0, t_q1, qb1, hnull, nullptr, nullptr, NV, nullptr);
    // clause MLP: fused clauses apply + cl gather/exp + output stats
    fc<<<mbC, T, FM_SMEM>>>(p_claus, nullptr, lit, p_cd, 128, 64, p_meanC, p_rsigC, cg, first,
                            t_c0, cb0, t_c1, cb1, hnull, nullptr, p_cd, NC, p_statC);
    // update MLP: fused uin gather + stats on vraw
    fu<<<mbV, T, FM_SMEM>>>(p_vars, nullptr, nullptr, hnull, 0, 0, nullptr, nullptr, vg, 0,
                            t_u0, ub0, t_u1, ub1, t_u2, ub2, p_vraw, NV, p_statV);
    k_fin2<<<B(2L*NG*64), T>>>();
  }

  k_head<<<mbC, T>>>(cg, t_o0, ob0, out, NC, oW1, ob1);

  (void)in_sizes; (void)n_in; (void)out_size;
}